// round 8
// baseline (speedup 1.0000x reference)
#include <cuda_runtime.h>
#include <cuda_bf16.h>
#include <cstdint>

// Problem constants (fixed by the dataset)
#define NN 50000
#define NE 1600000
#define NT 50
#define FDT 0.02f

// Persistent-kernel geometry: 444 = 148 SMs * 3 blocks, co-resident at <=40 regs
#define PBLK 444
#define THREADS 512
#define GPB (THREADS / 4)           // 128 groups of 4 lanes per block
#define NGROUPS (PBLK * GPB)        // 56832 >= NN -> exactly one row per group
#define CHUNK 113                   // ceil(NN / PBLK) for the grid scan
#define NBAR 64

// ---------------- device scratch (static, no allocations) ----------------
__device__ float2 g_csr[NE];            // per edge: {weight, bitcast(src)} sorted by TARGET
__device__ int    g_row_start[NN + 1];
__device__ int    g_deg[NN];
__device__ int    g_cursor[NN];
__device__ float  g_r[2][NN * 4];       // relu(v) rates, ping-pong, [node][batch]
__device__ float  g_alpha[NN];
__device__ int    g_bars[NBAR];         // per-barrier arrival counters (reset by init)
__device__ int    g_part[PBLK];         // scan partials

// ---------------- init kernel (resets barrier state each graph replay) ----------
__global__ void init_kernel(const float* __restrict__ bias,
                            const float* __restrict__ tc) {
    int i = blockIdx.x * blockDim.x + threadIdx.x;
    if (i < NBAR) g_bars[i] = 0;
    if (i < NN) {
        g_deg[i] = 0;
        g_cursor[i] = 0;
        g_alpha[i] = FDT / fmaxf(tc[i], FDT);
        float rb = fmaxf(bias[i], 0.0f);
        *reinterpret_cast<float4*>(&g_r[0][4 * i]) = make_float4(rb, rb, rb, rb);
    }
}

// ---------------- barriers ----------------
// Full barrier (prep phases): fences + L1 invalidate on both sides.
__device__ __forceinline__ void full_barrier(int idx) {
    __threadfence();
    __syncthreads();
    if (threadIdx.x == 0) {
        atomicAdd(&g_bars[idx], 1);
        volatile int* p = &g_bars[idx];
        while (*p < PBLK) { __nanosleep(64); }
    }
    __syncthreads();
    __threadfence();                    // acquire-side invalidate
}

// Light barrier (step loop): scoped release/acquire atomics, NO CCTL.IVALL,
// so the L1-resident CSR survives. All cross-step mutable data moves via
// ld.cg/st.cg (L2-only), so skipping the L1 invalidate is safe.
__device__ __forceinline__ void light_barrier(int idx) {
    __syncthreads();
    if (threadIdx.x == 0) {
        int* a = &g_bars[idx];
        asm volatile("red.release.gpu.add.u32 [%0], 1;" :: "l"(a) : "memory");
        unsigned v;
        do {
            asm volatile("ld.relaxed.gpu.u32 %0, [%1];" : "=r"(v) : "l"(a));
            if (v < PBLK) __nanosleep(32);
        } while (v < PBLK);
        unsigned d;
        asm volatile("atom.acquire.gpu.add.u32 %0, [%1], 0;"
                     : "=r"(d) : "l"(a) : "memory");
    }
    __syncthreads();
}

// ---------------- the whole problem in one persistent kernel ----------------
__global__ void __launch_bounds__(THREADS, 3)
net_kernel(const float* __restrict__ bias,
           const float* __restrict__ x,
           float* __restrict__ out,
           const int* __restrict__ src, const int* __restrict__ tgt,
           const float* __restrict__ sign, const float* __restrict__ cnt,
           const float* __restrict__ strg) {
    const int tid = threadIdx.x;
    const int bid = blockIdx.x;

    // ---------- phase 1: degree histogram (by target) ----------
    for (int i = bid * THREADS + tid; i < NE; i += PBLK * THREADS)
        atomicAdd(&g_deg[tgt[i]], 1);
    full_barrier(0);

    // ---------- phase 2: grid-wide exclusive scan of g_deg ----------
    {
        __shared__ int s_scan[THREADS];
        __shared__ int s_off;
        const int cbase = bid * CHUNK;
        int n = NN - cbase;
        if (n > CHUNK) n = CHUNK;
        if (n < 0) n = 0;
        int dval = (tid < n) ? g_deg[cbase + tid] : 0;
        s_scan[tid] = dval;
        __syncthreads();
        #pragma unroll
        for (int o = 1; o < THREADS; o <<= 1) {
            int v = (tid >= o) ? s_scan[tid - o] : 0;
            __syncthreads();
            s_scan[tid] += v;
            __syncthreads();
        }
        if (tid == 0) g_part[bid] = s_scan[THREADS - 1];
        full_barrier(1);
        {
            __shared__ int s_red[16];
            int acc = 0;
            for (int j = tid; j < bid; j += THREADS) acc += g_part[j];
            #pragma unroll
            for (int o = 16; o; o >>= 1) acc += __shfl_xor_sync(0xffffffffu, acc, o);
            if ((tid & 31) == 0) s_red[tid >> 5] = acc;
            __syncthreads();
            if (tid == 0) {
                int s = 0;
                #pragma unroll
                for (int w = 0; w < 16; w++) s += s_red[w];
                s_off = s;
            }
            __syncthreads();
        }
        if (tid < n) g_row_start[cbase + tid] = s_off + s_scan[tid] - dval;
        if (bid == PBLK - 1 && tid == 0) g_row_start[NN] = s_off + s_scan[THREADS - 1];
    }
    full_barrier(2);

    // ---------- phase 3: scatter edges into target-sorted CSR ----------
    for (int i = bid * THREADS + tid; i < NE; i += PBLK * THREADS) {
        float w = sign[i] * fmaxf(cnt[i], 0.0f) * fmaxf(strg[i], 0.0f);
        int t_ = tgt[i];
        int pos = atomicAdd(&g_cursor[t_], 1);
        g_csr[g_row_start[t_] + pos] = make_float2(w, __int_as_float(src[i]));
    }
    full_barrier(3);

    // ---------- phase 4: 50 recurrent steps ----------
    const int gid = bid * GPB + (tid >> 2);          // one row per 4-lane group
    const int lig = tid & 3;                         // lane in group == batch id
    const unsigned lbase = (unsigned)(tid & 31) & ~3u;
    const unsigned gmask = 0xFu << lbase;

    const bool ok = gid < NN;
    const int row = ok ? gid : 0;
    const int rs = ok ? g_row_start[row] : 0;
    const int re = ok ? g_row_start[row + 1] : 0;
    const float bi = ok ? __ldg(&bias[row]) : 0.0f;
    const float al = ok ? g_alpha[row] : 0.0f;
    float vb = bi;                                   // v starts at bias
    const int io_off = lig * NT * NN + row;          // 32-bit offsets save regs

    for (int t = 0; t < NT; t++) {
        const float* __restrict__ rates = g_r[t & 1];
        float* __restrict__       rnew  = g_r[(t & 1) ^ 1];
        const int toff = t * NN;

        float xv = ok ? __ldcg(&x[io_off + toff]) : 0.0f;

        float ax = 0.f, ay = 0.f, az = 0.f, aw = 0.f;
        int i = rs + lig;
        // 4 edges per lane per iteration (MLP = 4 outstanding L2 gathers)
        for (; i + 12 < re; i += 16) {
            float2 p0 = g_csr[i];                    // L1-resident across steps
            float2 p1 = g_csr[i + 4];
            float2 p2 = g_csr[i + 8];
            float2 p3 = g_csr[i + 12];
            float4 r0 = __ldcg(reinterpret_cast<const float4*>(
                                   rates + 4 * __float_as_int(p0.y)));
            float4 r1 = __ldcg(reinterpret_cast<const float4*>(
                                   rates + 4 * __float_as_int(p1.y)));
            float4 r2 = __ldcg(reinterpret_cast<const float4*>(
                                   rates + 4 * __float_as_int(p2.y)));
            float4 r3 = __ldcg(reinterpret_cast<const float4*>(
                                   rates + 4 * __float_as_int(p3.y)));
            ax = fmaf(r0.x, p0.x, ax); ay = fmaf(r0.y, p0.x, ay);
            az = fmaf(r0.z, p0.x, az); aw = fmaf(r0.w, p0.x, aw);
            ax = fmaf(r1.x, p1.x, ax); ay = fmaf(r1.y, p1.x, ay);
            az = fmaf(r1.z, p1.x, az); aw = fmaf(r1.w, p1.x, aw);
            ax = fmaf(r2.x, p2.x, ax); ay = fmaf(r2.y, p2.x, ay);
            az = fmaf(r2.z, p2.x, az); aw = fmaf(r2.w, p2.x, aw);
            ax = fmaf(r3.x, p3.x, ax); ay = fmaf(r3.y, p3.x, ay);
            az = fmaf(r3.z, p3.x, az); aw = fmaf(r3.w, p3.x, aw);
        }
        for (; i < re; i += 4) {
            float2 p0 = g_csr[i];
            float4 r0 = __ldcg(reinterpret_cast<const float4*>(
                                   rates + 4 * __float_as_int(p0.y)));
            ax = fmaf(r0.x, p0.x, ax); ay = fmaf(r0.y, p0.x, ay);
            az = fmaf(r0.z, p0.x, az); aw = fmaf(r0.w, p0.x, aw);
        }
        // reduce within the 4-lane group
        #pragma unroll
        for (int o = 2; o; o >>= 1) {
            ax += __shfl_xor_sync(gmask, ax, o, 4);
            ay += __shfl_xor_sync(gmask, ay, o, 4);
            az += __shfl_xor_sync(gmask, az, o, 4);
            aw += __shfl_xor_sync(gmask, aw, o, 4);
        }
        if (ok) {
            float sum = (lig == 0) ? ax : (lig == 1) ? ay : (lig == 2) ? az : aw;
            float vn = fmaf(al, bi - vb + sum + xv, vb);
            vb = vn;
            float rn = fmaxf(vn, 0.f);
            __stcg(&rnew[4 * row + lig], rn);        // L2-only: no stale L1 copies
            __stcs(&out[io_off + toff], rn);
        }

        if (t != NT - 1) light_barrier(4 + t);
    }
}

// ---------------- launch ----------------
extern "C" void kernel_launch(void* const* d_in, const int* in_sizes, int n_in,
                              void* d_out, int out_size) {
    const float* x      = (const float*)d_in[0];  // [B,T,N]
    const float* bias   = (const float*)d_in[1];  // [N]
    const float* tcst   = (const float*)d_in[2];  // [N]
    const float* sign   = (const float*)d_in[3];  // [E]
    const float* cnt    = (const float*)d_in[4];  // [E]
    const float* strg   = (const float*)d_in[5];  // [E]
    const int*   srcidx = (const int*)d_in[6];    // [E]
    const int*   tgtidx = (const int*)d_in[7];    // [E]
    float* out = (float*)d_out;                   // [B,T,N]

    const int nblk = (NN + 255) / 256;
    init_kernel<<<nblk, 256>>>(bias, tcst);
    net_kernel<<<PBLK, THREADS>>>(bias, x, out, srcidx, tgtidx, sign, cnt, strg);

    (void)in_sizes; (void)n_in; (void)out_size;
}